// round 2
// baseline (speedup 1.0000x reference)
#include <cuda_runtime.h>
#include <math.h>

#define NW    2048
#define NBINS 1024
#define NH    16
#define HD    64

// ---------------- scratch (device globals: allocation-free) ----------------
__device__ float g_lin[3][NW][NBINS];   // post-projection q/k/v (pre-conv)
__device__ float g_qkv[3][NW][NBINS];   // post-depthwise-conv q/k/v
__device__ float g_m[NH * NW];          // softmax row max
__device__ float g_l[NH * NW];          // softmax row sum
__device__ float g_o[NW][NBINS];        // attention output (pre-Wo)

// ---------------- generic 2048x1024x1024 fp32 SGEMM tile --------------------
// C[m0:m0+128, n0:n0+128] = A(2048x1024) @ B(1024x1024), row-major all.
__device__ __forceinline__ void sgemm_tile(const float* __restrict__ A,
                                           const float* __restrict__ B,
                                           float* __restrict__ C)
{
    __shared__ float As[16][129];   // A transposed: As[k][m]
    __shared__ float Bs[16][128];   // Bs[k][n]
    const int m0 = blockIdx.y * 128;
    const int n0 = blockIdx.x * 128;
    const int t  = threadIdx.x;
    const int tx = t & 15, ty = t >> 4;

    float acc[8][8];
#pragma unroll
    for (int u = 0; u < 8; u++)
#pragma unroll
        for (int v = 0; v < 8; v++) acc[u][v] = 0.f;

    for (int k0 = 0; k0 < 1024; k0 += 16) {
#pragma unroll
        for (int s = 0; s < 2; s++) {
            int e = t + 256 * s;
            int m = e >> 2, k4 = e & 3;
            float4 a = *(const float4*)&A[(size_t)(m0 + m) * 1024 + k0 + k4 * 4];
            As[k4 * 4 + 0][m] = a.x; As[k4 * 4 + 1][m] = a.y;
            As[k4 * 4 + 2][m] = a.z; As[k4 * 4 + 3][m] = a.w;
        }
#pragma unroll
        for (int s = 0; s < 2; s++) {
            int e = t + 256 * s;
            int k = e >> 5, c4 = e & 31;
            *(float4*)&Bs[k][c4 * 4] =
                *(const float4*)&B[(size_t)(k0 + k) * 1024 + n0 + c4 * 4];
        }
        __syncthreads();
#pragma unroll
        for (int kk = 0; kk < 16; kk++) {
            float a[8], b[8];
#pragma unroll
            for (int u = 0; u < 8; u++) a[u] = As[kk][ty * 8 + u];
#pragma unroll
            for (int v = 0; v < 8; v++) b[v] = Bs[kk][tx * 8 + v];
#pragma unroll
            for (int u = 0; u < 8; u++)
#pragma unroll
                for (int v = 0; v < 8; v++)
                    acc[u][v] = fmaf(a[u], b[v], acc[u][v]);
        }
        __syncthreads();
    }
#pragma unroll
    for (int u = 0; u < 8; u++) {
        size_t row = (size_t)(m0 + ty * 8 + u) * 1024 + n0 + tx * 8;
#pragma unroll
        for (int v4 = 0; v4 < 2; v4++) {
            float4 o;
            o.x = acc[u][v4 * 4 + 0]; o.y = acc[u][v4 * 4 + 1];
            o.z = acc[u][v4 * 4 + 2]; o.w = acc[u][v4 * 4 + 3];
            *(float4*)&C[row + v4 * 4] = o;
        }
    }
}

// K1: q/k/v projections, batched over blockIdx.z
__global__ void __launch_bounds__(256)
proj_kernel(const float* __restrict__ x, const float* __restrict__ Wq,
            const float* __restrict__ Wk, const float* __restrict__ Wv)
{
    const float* Bm = (blockIdx.z == 0) ? Wq : (blockIdx.z == 1 ? Wk : Wv);
    sgemm_tile(x, Bm, &g_lin[blockIdx.z][0][0]);
}

// K6: out = g_o @ Wo  (written to d_out[0 : 2048*1024])
__global__ void __launch_bounds__(256)
out_kernel(const float* __restrict__ Wo, float* __restrict__ out)
{
    sgemm_tile(&g_o[0][0], Wo, out);
}

// K2: depthwise conv along W, kernel=3, pad=1 (correlation, matches lax/torch)
__global__ void conv_kernel(const float* __restrict__ cq,
                            const float* __restrict__ ck,
                            const float* __restrict__ cv)
{
    int idx = blockIdx.x * 256 + threadIdx.x;            // 3*2048*1024 threads
    int z   = idx / (NW * NBINS);
    int rem = idx - z * (NW * NBINS);
    int w   = rem >> 10;
    int c   = rem & 1023;
    const float* cw = (z == 0) ? cq : (z == 1 ? ck : cv);
    float w0 = cw[c * 3 + 0], w1 = cw[c * 3 + 1], w2 = cw[c * 3 + 2];
    float acc = g_lin[z][w][c] * w1;
    if (w > 0)      acc += g_lin[z][w - 1][c] * w0;
    if (w < NW - 1) acc += g_lin[z][w + 1][c] * w2;
    g_qkv[z][w][c] = acc;
}

// K3: qk tile kernel. Computes for tile (i0,j0,h):
//   qk[i,j] = (Q[i]·K[j] + Rw[:,i]·Q[j]) / 32 + prev[i,j]
// Single d-loop (K=64), two FMAs per output element per d.
__global__ void __launch_bounds__(256)
qk_kernel(const float* __restrict__ relw, const float* __restrict__ prev,
          float* __restrict__ qk)
{
    extern __shared__ float sm[];
    float* sQi = sm;                 // [64][129]  sQi[d][r] = Q[i0+r, h*64+d]
    float* sRw = sm + 64 * 129;      // [64][129]  sRw[d][r] = relw[d, i0+r]
    float* sKj = sm + 2 * 64 * 129;  // [64][129]  sKj[d][c] = K[j0+c, h*64+d]
    float* sQj = sm + 3 * 64 * 129;  // [64][129]  sQj[d][c] = Q[j0+c, h*64+d]

    const int j0 = blockIdx.x * 128;
    const int i0 = blockIdx.y * 128;
    const int h  = blockIdx.z;
    const int t  = threadIdx.x;

    const float* Q  = &g_qkv[0][0][0];
    const float* Km = &g_qkv[1][0][0];

#pragma unroll
    for (int s = 0; s < 8; s++) {                        // 128 rows x 16 f4
        int e = t + 256 * s;
        int r = e >> 4, c4 = e & 15;
        float4 a = *(const float4*)&Q [(size_t)(i0 + r) * 1024 + h * 64 + c4 * 4];
        float4 b = *(const float4*)&Km[(size_t)(j0 + r) * 1024 + h * 64 + c4 * 4];
        float4 c = *(const float4*)&Q [(size_t)(j0 + r) * 1024 + h * 64 + c4 * 4];
        int d0 = c4 * 4;
        sQi[(d0 + 0) * 129 + r] = a.x; sQi[(d0 + 1) * 129 + r] = a.y;
        sQi[(d0 + 2) * 129 + r] = a.z; sQi[(d0 + 3) * 129 + r] = a.w;
        sKj[(d0 + 0) * 129 + r] = b.x; sKj[(d0 + 1) * 129 + r] = b.y;
        sKj[(d0 + 2) * 129 + r] = b.z; sKj[(d0 + 3) * 129 + r] = b.w;
        sQj[(d0 + 0) * 129 + r] = c.x; sQj[(d0 + 1) * 129 + r] = c.y;
        sQj[(d0 + 2) * 129 + r] = c.z; sQj[(d0 + 3) * 129 + r] = c.w;
    }
#pragma unroll
    for (int s = 0; s < 8; s++) {                        // 64 d x 32 f4
        int e = t + 256 * s;
        int d = e >> 5, c4 = e & 31;
        float4 rw = *(const float4*)&relw[(size_t)d * 2048 + i0 + c4 * 4];
        sRw[d * 129 + c4 * 4 + 0] = rw.x; sRw[d * 129 + c4 * 4 + 1] = rw.y;
        sRw[d * 129 + c4 * 4 + 2] = rw.z; sRw[d * 129 + c4 * 4 + 3] = rw.w;
    }
    __syncthreads();

    const int tx = t & 15, ty = t >> 4;
    const int r0 = ty * 8, c0 = tx * 8;
    float acc[8][8];
#pragma unroll
    for (int u = 0; u < 8; u++)
#pragma unroll
        for (int v = 0; v < 8; v++) acc[u][v] = 0.f;

#pragma unroll 4
    for (int d = 0; d < 64; d++) {
        float aQ[8], aR[8], bK[8], bQ[8];
#pragma unroll
        for (int u = 0; u < 8; u++) {
            aQ[u] = sQi[d * 129 + r0 + u];
            aR[u] = sRw[d * 129 + r0 + u];
        }
#pragma unroll
        for (int v = 0; v < 8; v++) {
            bK[v] = sKj[d * 129 + c0 + v];
            bQ[v] = sQj[d * 129 + c0 + v];
        }
#pragma unroll
        for (int u = 0; u < 8; u++)
#pragma unroll
            for (int v = 0; v < 8; v++) {
                acc[u][v] = fmaf(aQ[u], bK[v], acc[u][v]);
                acc[u][v] = fmaf(aR[u], bQ[v], acc[u][v]);
            }
    }

    const float inv = 1.0f / 32.0f;                      // 1/sqrt(1024)
    size_t base = ((size_t)h * 2048 + i0) * 2048 + j0;
#pragma unroll
    for (int u = 0; u < 8; u++) {
        size_t rowoff = base + (size_t)(r0 + u) * 2048 + c0;
#pragma unroll
        for (int v4 = 0; v4 < 2; v4++) {
            float4 p = *(const float4*)&prev[rowoff + v4 * 4];
            float4 o;
            o.x = acc[u][v4 * 4 + 0] * inv + p.x;
            o.y = acc[u][v4 * 4 + 1] * inv + p.y;
            o.z = acc[u][v4 * 4 + 2] * inv + p.z;
            o.w = acc[u][v4 * 4 + 3] * inv + p.w;
            *(float4*)&qk[rowoff + v4 * 4] = o;
        }
    }
}

// K4: per-row softmax stats (max, sum of exp) over 2048 cols
__global__ void __launch_bounds__(256)
rowstat_kernel(const float* __restrict__ qk)
{
    const int row = blockIdx.x;                          // 0..NH*NW-1
    const float* p = qk + (size_t)row * 2048;
    const int t = threadIdx.x;
    float v[8];
    float m = -1e30f;
#pragma unroll
    for (int s = 0; s < 8; s++) { v[s] = p[t + 256 * s]; m = fmaxf(m, v[s]); }
#pragma unroll
    for (int o = 16; o > 0; o >>= 1)
        m = fmaxf(m, __shfl_xor_sync(0xffffffffu, m, o));

    __shared__ float redm[8], reds[8];
    const int w = t >> 5, lane = t & 31;
    if (lane == 0) redm[w] = m;
    __syncthreads();
    float bm = fmaxf(fmaxf(fmaxf(redm[0], redm[1]), fmaxf(redm[2], redm[3])),
                     fmaxf(fmaxf(redm[4], redm[5]), fmaxf(redm[6], redm[7])));
    float sum = 0.f;
#pragma unroll
    for (int s = 0; s < 8; s++) sum += __expf(v[s] - bm);
#pragma unroll
    for (int o = 16; o > 0; o >>= 1)
        sum += __shfl_xor_sync(0xffffffffu, sum, o);
    if (lane == 0) reds[w] = sum;
    __syncthreads();
    if (t == 0) {
        g_m[row] = bm;
        g_l[row] = reds[0] + reds[1] + reds[2] + reds[3] +
                   reds[4] + reds[5] + reds[6] + reds[7];
    }
}

// K5: O[i0:i0+128, h*64:h*64+64] = softmax(qk) @ V  (exp on load, /l at end)
__global__ void __launch_bounds__(256)
av_kernel(const float* __restrict__ qk)
{
    extern __shared__ float sm[];
    float* sP = sm;                  // [128][132]
    float* sV = sm + 128 * 132;      // [128][68]
    const int i0 = blockIdx.x * 128;
    const int h  = blockIdx.y;
    const int t  = threadIdx.x;
    const int tx = t & 15, ty = t >> 4;
    const int r0 = ty * 8, c0 = tx * 4;

    float acc[8][4];
#pragma unroll
    for (int u = 0; u < 8; u++)
#pragma unroll
        for (int v = 0; v < 4; v++) acc[u][v] = 0.f;

    const float* V = &g_qkv[2][0][0];

    for (int jb = 0; jb < 16; jb++) {
        const int j0 = jb * 128;
#pragma unroll
        for (int s = 0; s < 16; s++) {                   // 128x128 qk tile
            int e = t + 256 * s;
            int r = e >> 5, c4 = e & 31;
            size_t off = ((size_t)(h * 2048 + i0 + r)) * 2048 + j0 + c4 * 4;
            float4 x = *(const float4*)&qk[off];
            float mrow = g_m[h * 2048 + i0 + r];
            float4 o;
            o.x = __expf(x.x - mrow);
            o.y = __expf(x.y - mrow);
            o.z = __expf(x.z - mrow);
            o.w = __expf(x.w - mrow);
            *(float4*)&sP[r * 132 + c4 * 4] = o;
        }
#pragma unroll
        for (int s = 0; s < 8; s++) {                    // 128x64 V tile (2048 f4)
            int e = t + 256 * s;
            int r = e >> 4, c4 = e & 15;
            *(float4*)&sV[r * 68 + c4 * 4] =
                *(const float4*)&V[(size_t)(j0 + r) * 1024 + h * 64 + c4 * 4];
        }
        __syncthreads();
#pragma unroll 2
        for (int jj = 0; jj < 128; jj++) {
            float4 vv = *(float4*)&sV[jj * 68 + c0];
#pragma unroll
            for (int u = 0; u < 8; u++) {
                float a = sP[(r0 + u) * 132 + jj];
                acc[u][0] = fmaf(a, vv.x, acc[u][0]);
                acc[u][1] = fmaf(a, vv.y, acc[u][1]);
                acc[u][2] = fmaf(a, vv.z, acc[u][2]);
                acc[u][3] = fmaf(a, vv.w, acc[u][3]);
            }
        }
        __syncthreads();
    }
#pragma unroll
    for (int u = 0; u < 8; u++) {
        float invl = 1.0f / g_l[h * 2048 + i0 + r0 + u];
        float4 o;
        o.x = acc[u][0] * invl; o.y = acc[u][1] * invl;
        o.z = acc[u][2] * invl; o.w = acc[u][3] * invl;
        *(float4*)&g_o[i0 + r0 + u][h * 64 + c0] = o;
    }
}

// --------------------------------------------------------------------------
extern "C" void kernel_launch(void* const* d_in, const int* in_sizes, int n_in,
                              void* d_out, int out_size)
{
    const float* x    = (const float*)d_in[0];
    const float* prev = (const float*)d_in[1];
    const float* Wq   = (const float*)d_in[2];
    const float* Wk   = (const float*)d_in[3];
    const float* Wv   = (const float*)d_in[4];
    const float* Wo   = (const float*)d_in[5];
    const float* cq   = (const float*)d_in[6];
    const float* ck   = (const float*)d_in[7];
    const float* cv   = (const float*)d_in[8];
    const float* relw = (const float*)d_in[9];

    float* out = (float*)d_out;                 // (1,2048,1024)
    float* qk  = out + (size_t)NW * NBINS;      // (1,16,2048,2048)

    const size_t QK_SMEM = (size_t)4 * 64 * 129 * sizeof(float);       // 132096
    const size_t AV_SMEM = (size_t)(128 * 132 + 128 * 68) * sizeof(float); // 102400
    cudaFuncSetAttribute(qk_kernel, cudaFuncAttributeMaxDynamicSharedMemorySize, (int)QK_SMEM);
    cudaFuncSetAttribute(av_kernel, cudaFuncAttributeMaxDynamicSharedMemorySize, (int)AV_SMEM);

    proj_kernel<<<dim3(8, 16, 3), 256>>>(x, Wq, Wk, Wv);
    conv_kernel<<<(3 * NW * NBINS) / 256, 256>>>(cq, ck, cv);
    qk_kernel<<<dim3(16, 16, 16), 256, QK_SMEM>>>(relw, prev, qk);
    rowstat_kernel<<<NH * NW, 256>>>(qk);
    av_kernel<<<dim3(16, 16), 256, AV_SMEM>>>(qk);
    out_kernel<<<dim3(8, 16), 256>>>(Wo, out);
}

// round 4
// speedup vs baseline: 1.3093x; 1.3093x over previous
#include <cuda_runtime.h>
#include <cuda_bf16.h>
#include <math.h>
#include <stdint.h>

#define NW    2048
#define NBINS 1024
#define NH    16
#define HD    64

// ---------------- scratch (device globals: allocation-free) ----------------
__device__ float g_lin[3][NW][NBINS];          // post-projection q/k/v (pre-conv)
__device__ float g_v[NW][NBINS];               // post-conv V (fp32 for SIMT AV)
__device__ __nv_bfloat16 g_qb[NW][NBINS];      // post-conv Q, bf16
__device__ __nv_bfloat16 g_kb[NW][NBINS];      // post-conv K, bf16
__device__ __nv_bfloat16 g_rwb[NW][HD];        // relw transposed: g_rwb[i][d]=relw[d][i]
__device__ float g_m[NH * NW];                 // softmax row max
__device__ float g_l[NH * NW];                 // softmax row sum
__device__ float g_o[NW][NBINS];               // attention output (pre-Wo)

// ======================= PTX helpers (generic sm_80+) ======================
__device__ __forceinline__ uint32_t smem_u32(const void* p) {
    uint32_t a;
    asm("{ .reg .u64 t; cvta.to.shared.u64 t, %1; cvt.u32.u64 %0, t; }"
        : "=r"(a) : "l"(p));
    return a;
}
__device__ __forceinline__ void ldm_x4(uint32_t r[4], uint32_t addr) {
    asm volatile("ldmatrix.sync.aligned.m8n8.x4.shared.b16 {%0,%1,%2,%3}, [%4];"
                 : "=r"(r[0]), "=r"(r[1]), "=r"(r[2]), "=r"(r[3]) : "r"(addr));
}
__device__ __forceinline__ void mma_16816(float c[4], const uint32_t a[4],
                                          uint32_t b0, uint32_t b1) {
    asm volatile(
        "mma.sync.aligned.m16n8k16.row.col.f32.bf16.bf16.f32 "
        "{%0,%1,%2,%3}, {%4,%5,%6,%7}, {%8,%9}, {%0,%1,%2,%3};"
        : "+f"(c[0]), "+f"(c[1]), "+f"(c[2]), "+f"(c[3])
        : "r"(a[0]), "r"(a[1]), "r"(a[2]), "r"(a[3]), "r"(b0), "r"(b1));
}

// ---------------- generic 2048x1024x1024 fp32 SGEMM tile --------------------
__device__ __forceinline__ void sgemm_tile(const float* __restrict__ A,
                                           const float* __restrict__ B,
                                           float* __restrict__ C)
{
    __shared__ float As[16][129];
    __shared__ float Bs[16][128];
    const int m0 = blockIdx.y * 128;
    const int n0 = blockIdx.x * 128;
    const int t  = threadIdx.x;
    const int tx = t & 15, ty = t >> 4;

    float acc[8][8];
#pragma unroll
    for (int u = 0; u < 8; u++)
#pragma unroll
        for (int v = 0; v < 8; v++) acc[u][v] = 0.f;

    for (int k0 = 0; k0 < 1024; k0 += 16) {
#pragma unroll
        for (int s = 0; s < 2; s++) {
            int e = t + 256 * s;
            int m = e >> 2, k4 = e & 3;
            float4 a = *(const float4*)&A[(size_t)(m0 + m) * 1024 + k0 + k4 * 4];
            As[k4 * 4 + 0][m] = a.x; As[k4 * 4 + 1][m] = a.y;
            As[k4 * 4 + 2][m] = a.z; As[k4 * 4 + 3][m] = a.w;
        }
#pragma unroll
        for (int s = 0; s < 2; s++) {
            int e = t + 256 * s;
            int k = e >> 5, c4 = e & 31;
            *(float4*)&Bs[k][c4 * 4] =
                *(const float4*)&B[(size_t)(k0 + k) * 1024 + n0 + c4 * 4];
        }
        __syncthreads();
#pragma unroll
        for (int kk = 0; kk < 16; kk++) {
            float a[8], b[8];
#pragma unroll
            for (int u = 0; u < 8; u++) a[u] = As[kk][ty * 8 + u];
#pragma unroll
            for (int v = 0; v < 8; v++) b[v] = Bs[kk][tx * 8 + v];
#pragma unroll
            for (int u = 0; u < 8; u++)
#pragma unroll
                for (int v = 0; v < 8; v++)
                    acc[u][v] = fmaf(a[u], b[v], acc[u][v]);
        }
        __syncthreads();
    }
#pragma unroll
    for (int u = 0; u < 8; u++) {
        size_t row = (size_t)(m0 + ty * 8 + u) * 1024 + n0 + tx * 8;
#pragma unroll
        for (int v4 = 0; v4 < 2; v4++) {
            float4 o;
            o.x = acc[u][v4 * 4 + 0]; o.y = acc[u][v4 * 4 + 1];
            o.z = acc[u][v4 * 4 + 2]; o.w = acc[u][v4 * 4 + 3];
            *(float4*)&C[row + v4 * 4] = o;
        }
    }
}

// K1: q/k/v projections
__global__ void __launch_bounds__(256)
proj_kernel(const float* __restrict__ x, const float* __restrict__ Wq,
            const float* __restrict__ Wk, const float* __restrict__ Wv)
{
    const float* Bm = (blockIdx.z == 0) ? Wq : (blockIdx.z == 1 ? Wk : Wv);
    sgemm_tile(x, Bm, &g_lin[blockIdx.z][0][0]);
}

// K6: out = g_o @ Wo
__global__ void __launch_bounds__(256)
out_kernel(const float* __restrict__ Wo, float* __restrict__ out)
{
    sgemm_tile(&g_o[0][0], Wo, out);
}

// K2: depthwise conv; Q,K emitted as bf16, V as fp32
__global__ void conv_kernel(const float* __restrict__ cq,
                            const float* __restrict__ ck,
                            const float* __restrict__ cv)
{
    int idx = blockIdx.x * 256 + threadIdx.x;
    int z   = idx / (NW * NBINS);
    int rem = idx - z * (NW * NBINS);
    int w   = rem >> 10;
    int c   = rem & 1023;
    const float* cw = (z == 0) ? cq : (z == 1 ? ck : cv);
    float w0 = cw[c * 3 + 0], w1 = cw[c * 3 + 1], w2 = cw[c * 3 + 2];
    float acc = g_lin[z][w][c] * w1;
    if (w > 0)      acc += g_lin[z][w - 1][c] * w0;
    if (w < NW - 1) acc += g_lin[z][w + 1][c] * w2;
    if (z == 0)      g_qb[w][c] = __float2bfloat16(acc);
    else if (z == 1) g_kb[w][c] = __float2bfloat16(acc);
    else             g_v[w][c]  = acc;
}

// K2b: relw transpose + bf16 convert
__global__ void relw_cvt_kernel(const float* __restrict__ relw)
{
    int idx = blockIdx.x * 256 + threadIdx.x;   // 64*2048
    int d = idx >> 11, i = idx & 2047;
    g_rwb[i][d] = __float2bfloat16(relw[idx]);
}

// K3: qk via mma.sync bf16 (HMMA fallback path; tcgen05 unavailable on
// family-generic compute_103 PTX target).
// Tile (i0,j0,h): D = Qi(128x64)@Kj^T + Rwi(128x64)@Qj^T; qk = D/32 + prev.
// 8 warps, each owns a 64x32 warp tile (wm = wid&1 row half, wn = wid>>1 col quarter).
#define QK_RS 72   // padded row stride in bf16 units (144 B)
__global__ void __launch_bounds__(256)
qk_mma_kernel(const float* __restrict__ prev, float* __restrict__ qk)
{
    extern __shared__ __nv_bfloat16 smb[];
    __nv_bfloat16* sQi = smb;                   // [128][72]
    __nv_bfloat16* sKj = smb + 128 * QK_RS;
    __nv_bfloat16* sQj = smb + 2 * 128 * QK_RS;
    __nv_bfloat16* sRw = smb + 3 * 128 * QK_RS;

    const int t = threadIdx.x, wid = t >> 5, lane = t & 31;
    const int j0 = blockIdx.x * 128, i0 = blockIdx.y * 128, h = blockIdx.z;

    // Load 4 tiles [128 rows x 64 bf16 = 128 B/row]. 2 threads/row, 4 uint4 each.
    {
        const int r = t & 127;
        const int ch0 = (t >> 7) * 4;
        const uint4* qi = (const uint4*)&g_qb[i0 + r][h * 64];
        const uint4* kj = (const uint4*)&g_kb[j0 + r][h * 64];
        const uint4* qj = (const uint4*)&g_qb[j0 + r][h * 64];
        const uint4* rw = (const uint4*)&g_rwb[i0 + r][0];
#pragma unroll
        for (int c = 0; c < 4; c++) {
            int c16 = ch0 + c;
            *(uint4*)((char*)sQi + r * 144 + c16 * 16) = qi[c16];
            *(uint4*)((char*)sKj + r * 144 + c16 * 16) = kj[c16];
            *(uint4*)((char*)sQj + r * 144 + c16 * 16) = qj[c16];
            *(uint4*)((char*)sRw + r * 144 + c16 * 16) = rw[c16];
        }
    }
    __syncthreads();

    const int wm = wid & 1;        // 0..1 -> 64-row half
    const int wn = wid >> 1;       // 0..3 -> 32-col quarter
    const uint32_t sbQi = smem_u32(sQi), sbKj = smem_u32(sKj);
    const uint32_t sbQj = smem_u32(sQj), sbRw = smem_u32(sRw);

    float c[4][4][4];
#pragma unroll
    for (int mi = 0; mi < 4; mi++)
#pragma unroll
        for (int ni = 0; ni < 4; ni++)
#pragma unroll
            for (int e = 0; e < 4; e++) c[mi][ni][e] = 0.f;

#pragma unroll
    for (int term = 0; term < 2; term++) {
        const uint32_t sbA = term ? sbRw : sbQi;
        const uint32_t sbB = term ? sbQj : sbKj;
#pragma unroll
        for (int ks = 0; ks < 4; ks++) {
            const int kcol = ks * 16 + (lane >> 4) * 8;      // bf16 col for ldmatrix
            uint32_t a[4][4];
#pragma unroll
            for (int mi = 0; mi < 4; mi++) {
                int row = wm * 64 + mi * 16 + (lane & 15);
                ldm_x4(a[mi], sbA + (uint32_t)(row * 144 + kcol * 2));
            }
            uint32_t b[4][2];
#pragma unroll
            for (int nh = 0; nh < 2; nh++) {
                int row = wn * 32 + nh * 16 + (lane & 15);
                uint32_t r4[4];
                ldm_x4(r4, sbB + (uint32_t)(row * 144 + kcol * 2));
                b[nh * 2 + 0][0] = r4[0]; b[nh * 2 + 0][1] = r4[2];
                b[nh * 2 + 1][0] = r4[1]; b[nh * 2 + 1][1] = r4[3];
            }
#pragma unroll
            for (int mi = 0; mi < 4; mi++)
#pragma unroll
                for (int ni = 0; ni < 4; ni++)
                    mma_16816(c[mi][ni], a[mi], b[ni][0], b[ni][1]);
        }
    }

    // Epilogue: qk = c/32 + prev
    const float inv = 1.0f / 32.0f;
    const int qr = lane >> 2, qc = (lane & 3) * 2;
#pragma unroll
    for (int mi = 0; mi < 4; mi++) {
#pragma unroll
        for (int ni = 0; ni < 4; ni++) {
#pragma unroll
            for (int half = 0; half < 2; half++) {
                int row = i0 + wm * 64 + mi * 16 + qr + half * 8;
                int col = j0 + wn * 32 + ni * 8 + qc;
                size_t off = ((size_t)(h * 2048) + row) * 2048 + col;
                float2 p = *(const float2*)&prev[off];
                float2 o;
                o.x = c[mi][ni][half * 2 + 0] * inv + p.x;
                o.y = c[mi][ni][half * 2 + 1] * inv + p.y;
                *(float2*)&qk[off] = o;
            }
        }
    }
}

// K4: per-row softmax stats (max, sum of exp) over 2048 cols
__global__ void __launch_bounds__(256)
rowstat_kernel(const float* __restrict__ qk)
{
    const int row = blockIdx.x;
    const float* p = qk + (size_t)row * 2048;
    const int t = threadIdx.x;
    float v[8];
    float m = -1e30f;
#pragma unroll
    for (int s = 0; s < 8; s++) { v[s] = p[t + 256 * s]; m = fmaxf(m, v[s]); }
#pragma unroll
    for (int o = 16; o > 0; o >>= 1)
        m = fmaxf(m, __shfl_xor_sync(0xffffffffu, m, o));

    __shared__ float redm[8], reds[8];
    const int w = t >> 5, lane = t & 31;
    if (lane == 0) redm[w] = m;
    __syncthreads();
    float bm = fmaxf(fmaxf(fmaxf(redm[0], redm[1]), fmaxf(redm[2], redm[3])),
                     fmaxf(fmaxf(redm[4], redm[5]), fmaxf(redm[6], redm[7])));
    float sum = 0.f;
#pragma unroll
    for (int s = 0; s < 8; s++) sum += __expf(v[s] - bm);
#pragma unroll
    for (int o = 16; o > 0; o >>= 1)
        sum += __shfl_xor_sync(0xffffffffu, sum, o);
    if (lane == 0) reds[w] = sum;
    __syncthreads();
    if (t == 0) {
        g_m[row] = bm;
        g_l[row] = reds[0] + reds[1] + reds[2] + reds[3] +
                   reds[4] + reds[5] + reds[6] + reds[7];
    }
}

// K5: O[i0:i0+128, h*64:h*64+64] = softmax(qk) @ V
__global__ void __launch_bounds__(256)
av_kernel(const float* __restrict__ qk)
{
    extern __shared__ float sm[];
    float* sP = sm;                  // [128][132]
    float* sV = sm + 128 * 132;      // [128][68]
    const int i0 = blockIdx.x * 128;
    const int h  = blockIdx.y;
    const int t  = threadIdx.x;
    const int tx = t & 15, ty = t >> 4;
    const int r0 = ty * 8, c0 = tx * 4;

    float acc[8][4];
#pragma unroll
    for (int u = 0; u < 8; u++)
#pragma unroll
        for (int v = 0; v < 4; v++) acc[u][v] = 0.f;

    const float* V = &g_v[0][0];

    for (int jb = 0; jb < 16; jb++) {
        const int j0 = jb * 128;
#pragma unroll
        for (int s = 0; s < 16; s++) {
            int e = t + 256 * s;
            int r = e >> 5, c4 = e & 31;
            size_t off = ((size_t)(h * 2048 + i0 + r)) * 2048 + j0 + c4 * 4;
            float4 x = *(const float4*)&qk[off];
            float mrow = g_m[h * 2048 + i0 + r];
            float4 o;
            o.x = __expf(x.x - mrow);
            o.y = __expf(x.y - mrow);
            o.z = __expf(x.z - mrow);
            o.w = __expf(x.w - mrow);
            *(float4*)&sP[r * 132 + c4 * 4] = o;
        }
#pragma unroll
        for (int s = 0; s < 8; s++) {
            int e = t + 256 * s;
            int r = e >> 4, c4 = e & 15;
            *(float4*)&sV[r * 68 + c4 * 4] =
                *(const float4*)&V[(size_t)(j0 + r) * 1024 + h * 64 + c4 * 4];
        }
        __syncthreads();
#pragma unroll 2
        for (int jj = 0; jj < 128; jj++) {
            float4 vv = *(float4*)&sV[jj * 68 + c0];
#pragma unroll
            for (int u = 0; u < 8; u++) {
                float a = sP[(r0 + u) * 132 + jj];
                acc[u][0] = fmaf(a, vv.x, acc[u][0]);
                acc[u][1] = fmaf(a, vv.y, acc[u][1]);
                acc[u][2] = fmaf(a, vv.z, acc[u][2]);
                acc[u][3] = fmaf(a, vv.w, acc[u][3]);
            }
        }
        __syncthreads();
    }
#pragma unroll
    for (int u = 0; u < 8; u++) {
        float invl = 1.0f / g_l[h * 2048 + i0 + r0 + u];
        float4 o;
        o.x = acc[u][0] * invl; o.y = acc[u][1] * invl;
        o.z = acc[u][2] * invl; o.w = acc[u][3] * invl;
        *(float4*)&g_o[i0 + r0 + u][h * 64 + c0] = o;
    }
}

// --------------------------------------------------------------------------
extern "C" void kernel_launch(void* const* d_in, const int* in_sizes, int n_in,
                              void* d_out, int out_size)
{
    const float* x    = (const float*)d_in[0];
    const float* prev = (const float*)d_in[1];
    const float* Wq   = (const float*)d_in[2];
    const float* Wk   = (const float*)d_in[3];
    const float* Wv   = (const float*)d_in[4];
    const float* Wo   = (const float*)d_in[5];
    const float* cq   = (const float*)d_in[6];
    const float* ck   = (const float*)d_in[7];
    const float* cv   = (const float*)d_in[8];
    const float* relw = (const float*)d_in[9];

    float* out = (float*)d_out;                 // (1,2048,1024)
    float* qk  = out + (size_t)NW * NBINS;      // (1,16,2048,2048)

    const size_t QK_SMEM = (size_t)4 * 128 * QK_RS * sizeof(__nv_bfloat16); // 73728
    const size_t AV_SMEM = (size_t)(128 * 132 + 128 * 68) * sizeof(float);  // 102400
    cudaFuncSetAttribute(qk_mma_kernel, cudaFuncAttributeMaxDynamicSharedMemorySize, (int)QK_SMEM);
    cudaFuncSetAttribute(av_kernel, cudaFuncAttributeMaxDynamicSharedMemorySize, (int)AV_SMEM);

    proj_kernel<<<dim3(8, 16, 3), 256>>>(x, Wq, Wk, Wv);
    conv_kernel<<<(3 * NW * NBINS) / 256, 256>>>(cq, ck, cv);
    relw_cvt_kernel<<<(HD * NW) / 256, 256>>>(relw);
    qk_mma_kernel<<<dim3(16, 16, 16), 256, QK_SMEM>>>(prev, qk);
    rowstat_kernel<<<NH * NW, 256>>>(qk);
    av_kernel<<<dim3(16, 16), 256, AV_SMEM>>>(qk);
    out_kernel<<<dim3(8, 16), 256>>>(Wo, out);
}

// round 5
// speedup vs baseline: 2.2244x; 1.6990x over previous
#include <cuda_runtime.h>
#include <cuda_bf16.h>
#include <math.h>
#include <stdint.h>

#define NW    2048
#define NBINS 1024
#define NH    16
#define HD    64

// ---------------- scratch (device globals: allocation-free) ----------------
__device__ float g_lin[3][NW][NBINS];          // post-projection q/k/v (pre-conv)
__device__ float g_v[NW][NBINS];               // post-conv V fp32
__device__ __nv_bfloat16 g_qb[NW][NBINS];      // post-conv Q, bf16
__device__ __nv_bfloat16 g_kb[NW][NBINS];      // post-conv K, bf16
__device__ __nv_bfloat16 g_rwb[NW][HD];        // relw^T bf16
__device__ __nv_bfloat16 g_vth[NH][HD][NW];    // V^T per head, hi part
__device__ __nv_bfloat16 g_vtl[NH][HD][NW];    // V^T per head, lo part
__device__ float g_m[NH * NW];                 // softmax row max
__device__ float g_l[NH * NW];                 // softmax row sum
__device__ float g_o[NW][NBINS];               // attention output (pre-Wo)

// ======================= PTX helpers (generic sm_80+) ======================
__device__ __forceinline__ uint32_t smem_u32(const void* p) {
    uint32_t a;
    asm("{ .reg .u64 t; cvta.to.shared.u64 t, %1; cvt.u32.u64 %0, t; }"
        : "=r"(a) : "l"(p));
    return a;
}
__device__ __forceinline__ void ldm_x4(uint32_t r[4], uint32_t addr) {
    asm volatile("ldmatrix.sync.aligned.m8n8.x4.shared.b16 {%0,%1,%2,%3}, [%4];"
                 : "=r"(r[0]), "=r"(r[1]), "=r"(r[2]), "=r"(r[3]) : "r"(addr));
}
__device__ __forceinline__ void ldm_x4_t(uint32_t r[4], uint32_t addr) {
    asm volatile("ldmatrix.sync.aligned.m8n8.x4.trans.shared.b16 {%0,%1,%2,%3}, [%4];"
                 : "=r"(r[0]), "=r"(r[1]), "=r"(r[2]), "=r"(r[3]) : "r"(addr));
}
__device__ __forceinline__ void mma_16816(float c[4], const uint32_t a[4],
                                          uint32_t b0, uint32_t b1) {
    asm volatile(
        "mma.sync.aligned.m16n8k16.row.col.f32.bf16.bf16.f32 "
        "{%0,%1,%2,%3}, {%4,%5,%6,%7}, {%8,%9}, {%0,%1,%2,%3};"
        : "+f"(c[0]), "+f"(c[1]), "+f"(c[2]), "+f"(c[3])
        : "r"(a[0]), "r"(a[1]), "r"(a[2]), "r"(a[3]), "r"(b0), "r"(b1));
}
// split a float4 into hi/lo bf16 quads and store (8B each)
__device__ __forceinline__ void split_store(float4 v, __nv_bfloat16* ph,
                                            __nv_bfloat16* pl) {
    __nv_bfloat16 hh[4], ll[4];
#pragma unroll
    for (int i = 0; i < 4; i++) {
        float f = (&v.x)[i];
        hh[i] = __float2bfloat16(f);
        ll[i] = __float2bfloat16(f - __bfloat162float(hh[i]));
    }
    *(uint2*)ph = *(uint2*)hh;
    *(uint2*)pl = *(uint2*)ll;
}

// ================= split-bf16 tensor GEMM: C = A(2048x1024) @ B(1024x1024) ==
// 128x128 block tile, k-chunk 64, 3-term split mma (hh + lh + hl).
#define GS_SMEM 71680
__device__ __forceinline__ void gemm_split(const float* __restrict__ A,
                                           const float* __restrict__ B,
                                           float* __restrict__ C)
{
    extern __shared__ __nv_bfloat16 gs[];
    __nv_bfloat16* sAh = gs;                // [128][72]
    __nv_bfloat16* sAl = gs + 9216;
    __nv_bfloat16* sBh = gs + 18432;        // [64][136]  (k-major)
    __nv_bfloat16* sBl = gs + 27136;
    const int t = threadIdx.x, wid = t >> 5, lane = t & 31;
    const int m0 = blockIdx.y * 128, n0 = blockIdx.x * 128;
    const int wm = wid >> 1, wn = wid & 1;  // warp tile 32(m) x 64(n)

    float acc[2][8][4];
#pragma unroll
    for (int mi = 0; mi < 2; mi++)
#pragma unroll
        for (int o = 0; o < 8; o++)
#pragma unroll
            for (int e = 0; e < 4; e++) acc[mi][o][e] = 0.f;

    for (int k0 = 0; k0 < 1024; k0 += 64) {
#pragma unroll
        for (int s = 0; s < 8; s++) {                 // A 128x64
            int e = t + 256 * s;
            int r = e >> 4, c4 = e & 15;
            float4 a = *(const float4*)&A[(size_t)(m0 + r) * 1024 + k0 + c4 * 4];
            split_store(a, &sAh[r * 72 + c4 * 4], &sAl[r * 72 + c4 * 4]);
        }
#pragma unroll
        for (int s = 0; s < 8; s++) {                 // B 64x128
            int e = t + 256 * s;
            int kr = e >> 5, c4 = e & 31;
            float4 b = *(const float4*)&B[(size_t)(k0 + kr) * 1024 + n0 + c4 * 4];
            split_store(b, &sBh[kr * 136 + c4 * 4], &sBl[kr * 136 + c4 * 4]);
        }
        __syncthreads();
        const uint32_t bAh = smem_u32(sAh), bAl = smem_u32(sAl);
        const uint32_t bBh = smem_u32(sBh), bBl = smem_u32(sBl);
        const int g = lane >> 3;
#pragma unroll
        for (int kk = 0; kk < 64; kk += 16) {
            uint32_t ah[2][4], al[2][4], bb[8][2];
#pragma unroll
            for (int mi = 0; mi < 2; mi++) {
                uint32_t off = (uint32_t)((wm * 32 + mi * 16 + (lane & 15)) * 72
                                          + kk + (lane >> 4) * 8) * 2;
                ldm_x4(ah[mi], bAh + off);
                ldm_x4(al[mi], bAl + off);
            }
#pragma unroll
            for (int g4 = 0; g4 < 4; g4++) {          // B hi frags via trans
                uint32_t off = (uint32_t)((kk + (g >> 1) * 8 + (lane & 7)) * 136
                                          + wn * 64 + g4 * 16 + (g & 1) * 8) * 2;
                uint32_t r4[4];
                ldm_x4_t(r4, bBh + off);
                bb[g4 * 2 + 0][0] = r4[0]; bb[g4 * 2 + 0][1] = r4[2];
                bb[g4 * 2 + 1][0] = r4[1]; bb[g4 * 2 + 1][1] = r4[3];
            }
#pragma unroll
            for (int mi = 0; mi < 2; mi++)
#pragma unroll
                for (int o = 0; o < 8; o++)
                    mma_16816(acc[mi][o], ah[mi], bb[o][0], bb[o][1]);
#pragma unroll
            for (int mi = 0; mi < 2; mi++)
#pragma unroll
                for (int o = 0; o < 8; o++)
                    mma_16816(acc[mi][o], al[mi], bb[o][0], bb[o][1]);
#pragma unroll
            for (int g4 = 0; g4 < 4; g4++) {          // B lo frags
                uint32_t off = (uint32_t)((kk + (g >> 1) * 8 + (lane & 7)) * 136
                                          + wn * 64 + g4 * 16 + (g & 1) * 8) * 2;
                uint32_t r4[4];
                ldm_x4_t(r4, bBl + off);
                bb[g4 * 2 + 0][0] = r4[0]; bb[g4 * 2 + 0][1] = r4[2];
                bb[g4 * 2 + 1][0] = r4[1]; bb[g4 * 2 + 1][1] = r4[3];
            }
#pragma unroll
            for (int mi = 0; mi < 2; mi++)
#pragma unroll
                for (int o = 0; o < 8; o++)
                    mma_16816(acc[mi][o], ah[mi], bb[o][0], bb[o][1]);
        }
        __syncthreads();
    }
#pragma unroll
    for (int mi = 0; mi < 2; mi++)
#pragma unroll
        for (int o = 0; o < 8; o++)
#pragma unroll
            for (int half = 0; half < 2; half++) {
                int row = m0 + wm * 32 + mi * 16 + (lane >> 2) + half * 8;
                int col = n0 + wn * 64 + o * 8 + (lane & 3) * 2;
                float2 w;
                w.x = acc[mi][o][half * 2 + 0];
                w.y = acc[mi][o][half * 2 + 1];
                *(float2*)&C[(size_t)row * 1024 + col] = w;
            }
}

// K1: q/k/v projections (tensor, split-bf16)
__global__ void __launch_bounds__(256, 2)
proj_mma_kernel(const float* __restrict__ x, const float* __restrict__ Wq,
                const float* __restrict__ Wk, const float* __restrict__ Wv)
{
    const float* B = (blockIdx.z == 0) ? Wq : (blockIdx.z == 1 ? Wk : Wv);
    gemm_split(x, B, &g_lin[blockIdx.z][0][0]);
}

// K8: out = g_o @ Wo (tensor, split-bf16)
__global__ void __launch_bounds__(256, 2)
out_mma_kernel(const float* __restrict__ Wo, float* __restrict__ out)
{
    gemm_split(&g_o[0][0], Wo, out);
}

// K2: depthwise conv; Q,K as bf16, V fp32
__global__ void conv_kernel(const float* __restrict__ cq,
                            const float* __restrict__ ck,
                            const float* __restrict__ cv)
{
    int idx = blockIdx.x * 256 + threadIdx.x;
    int z   = idx / (NW * NBINS);
    int rem = idx - z * (NW * NBINS);
    int w   = rem >> 10;
    int c   = rem & 1023;
    const float* cw = (z == 0) ? cq : (z == 1 ? ck : cv);
    float w0 = cw[c * 3 + 0], w1 = cw[c * 3 + 1], w2 = cw[c * 3 + 2];
    float acc = g_lin[z][w][c] * w1;
    if (w > 0)      acc += g_lin[z][w - 1][c] * w0;
    if (w < NW - 1) acc += g_lin[z][w + 1][c] * w2;
    if (z == 0)      g_qb[w][c] = __float2bfloat16(acc);
    else if (z == 1) g_kb[w][c] = __float2bfloat16(acc);
    else             g_v[w][c]  = acc;
}

// K2b: relw transpose + bf16 convert
__global__ void relw_cvt_kernel(const float* __restrict__ relw)
{
    int idx = blockIdx.x * 256 + threadIdx.x;   // 64*2048
    int d = idx >> 11, i = idx & 2047;
    g_rwb[i][d] = __float2bfloat16(relw[idx]);
}

// K2c: V -> per-head transposed hi/lo bf16 (tiled 64x64 transpose)
__global__ void __launch_bounds__(256)
vt_split_kernel()
{
    __shared__ float tile[64][65];
    const int w0 = blockIdx.x * 64, h = blockIdx.y;
    const int t = threadIdx.x;
#pragma unroll
    for (int s = 0; s < 4; s++) {
        int e = t + 256 * s;
        int r = e >> 4, c4 = e & 15;
        float4 v = *(const float4*)&g_v[w0 + r][h * 64 + c4 * 4];
        tile[r][c4 * 4 + 0] = v.x; tile[r][c4 * 4 + 1] = v.y;
        tile[r][c4 * 4 + 2] = v.z; tile[r][c4 * 4 + 3] = v.w;
    }
    __syncthreads();
#pragma unroll
    for (int s = 0; s < 4; s++) {
        int e = t + 256 * s;
        int d = e >> 4, w4 = e & 15;
        __nv_bfloat16 hh[4], ll[4];
#pragma unroll
        for (int i = 0; i < 4; i++) {
            float f = tile[w4 * 4 + i][d];
            hh[i] = __float2bfloat16(f);
            ll[i] = __float2bfloat16(f - __bfloat162float(hh[i]));
        }
        *(uint2*)&g_vth[h][d][w0 + w4 * 4] = *(uint2*)hh;
        *(uint2*)&g_vtl[h][d][w0 + w4 * 4] = *(uint2*)ll;
    }
}

// K3: qk via mma.sync bf16 (unchanged from R4)
#define QK_RS 72
__global__ void __launch_bounds__(256)
qk_mma_kernel(const float* __restrict__ prev, float* __restrict__ qk)
{
    extern __shared__ __nv_bfloat16 smb[];
    __nv_bfloat16* sQi = smb;
    __nv_bfloat16* sKj = smb + 128 * QK_RS;
    __nv_bfloat16* sQj = smb + 2 * 128 * QK_RS;
    __nv_bfloat16* sRw = smb + 3 * 128 * QK_RS;

    const int t = threadIdx.x, wid = t >> 5, lane = t & 31;
    const int j0 = blockIdx.x * 128, i0 = blockIdx.y * 128, h = blockIdx.z;

    {
        const int r = t & 127;
        const int ch0 = (t >> 7) * 4;
        const uint4* qi = (const uint4*)&g_qb[i0 + r][h * 64];
        const uint4* kj = (const uint4*)&g_kb[j0 + r][h * 64];
        const uint4* qj = (const uint4*)&g_qb[j0 + r][h * 64];
        const uint4* rw = (const uint4*)&g_rwb[i0 + r][0];
#pragma unroll
        for (int c = 0; c < 4; c++) {
            int c16 = ch0 + c;
            *(uint4*)((char*)sQi + r * 144 + c16 * 16) = qi[c16];
            *(uint4*)((char*)sKj + r * 144 + c16 * 16) = kj[c16];
            *(uint4*)((char*)sQj + r * 144 + c16 * 16) = qj[c16];
            *(uint4*)((char*)sRw + r * 144 + c16 * 16) = rw[c16];
        }
    }
    __syncthreads();

    const int wm = wid & 1;
    const int wn = wid >> 1;
    const uint32_t sbQi = smem_u32(sQi), sbKj = smem_u32(sKj);
    const uint32_t sbQj = smem_u32(sQj), sbRw = smem_u32(sRw);

    float c[4][4][4];
#pragma unroll
    for (int mi = 0; mi < 4; mi++)
#pragma unroll
        for (int ni = 0; ni < 4; ni++)
#pragma unroll
            for (int e = 0; e < 4; e++) c[mi][ni][e] = 0.f;

#pragma unroll
    for (int term = 0; term < 2; term++) {
        const uint32_t sbA = term ? sbRw : sbQi;
        const uint32_t sbB = term ? sbQj : sbKj;
#pragma unroll
        for (int ks = 0; ks < 4; ks++) {
            const int kcol = ks * 16 + (lane >> 4) * 8;
            uint32_t a[4][4];
#pragma unroll
            for (int mi = 0; mi < 4; mi++) {
                int row = wm * 64 + mi * 16 + (lane & 15);
                ldm_x4(a[mi], sbA + (uint32_t)(row * 144 + kcol * 2));
            }
            uint32_t b[4][2];
#pragma unroll
            for (int nh = 0; nh < 2; nh++) {
                int row = wn * 32 + nh * 16 + (lane & 15);
                uint32_t r4[4];
                ldm_x4(r4, sbB + (uint32_t)(row * 144 + kcol * 2));
                b[nh * 2 + 0][0] = r4[0]; b[nh * 2 + 0][1] = r4[2];
                b[nh * 2 + 1][0] = r4[1]; b[nh * 2 + 1][1] = r4[3];
            }
#pragma unroll
            for (int mi = 0; mi < 4; mi++)
#pragma unroll
                for (int ni = 0; ni < 4; ni++)
                    mma_16816(c[mi][ni], a[mi], b[ni][0], b[ni][1]);
        }
    }

    const float inv = 1.0f / 32.0f;
    const int qr = lane >> 2, qc = (lane & 3) * 2;
#pragma unroll
    for (int mi = 0; mi < 4; mi++) {
#pragma unroll
        for (int ni = 0; ni < 4; ni++) {
#pragma unroll
            for (int half = 0; half < 2; half++) {
                int row = i0 + wm * 64 + mi * 16 + qr + half * 8;
                int col = j0 + wn * 32 + ni * 8 + qc;
                size_t off = ((size_t)(h * 2048) + row) * 2048 + col;
                float2 p = *(const float2*)&prev[off];
                float2 o;
                o.x = c[mi][ni][half * 2 + 0] * inv + p.x;
                o.y = c[mi][ni][half * 2 + 1] * inv + p.y;
                *(float2*)&qk[off] = o;
            }
        }
    }
}

// K4: per-row softmax stats
__global__ void __launch_bounds__(256)
rowstat_kernel(const float* __restrict__ qk)
{
    const int row = blockIdx.x;
    const float* p = qk + (size_t)row * 2048;
    const int t = threadIdx.x;
    float v[8];
    float m = -1e30f;
#pragma unroll
    for (int s = 0; s < 8; s++) { v[s] = p[t + 256 * s]; m = fmaxf(m, v[s]); }
#pragma unroll
    for (int o = 16; o > 0; o >>= 1)
        m = fmaxf(m, __shfl_xor_sync(0xffffffffu, m, o));

    __shared__ float redm[8], reds[8];
    const int w = t >> 5, lane = t & 31;
    if (lane == 0) redm[w] = m;
    __syncthreads();
    float bm = fmaxf(fmaxf(fmaxf(redm[0], redm[1]), fmaxf(redm[2], redm[3])),
                     fmaxf(fmaxf(redm[4], redm[5]), fmaxf(redm[6], redm[7])));
    float sum = 0.f;
#pragma unroll
    for (int s = 0; s < 8; s++) sum += __expf(v[s] - bm);
#pragma unroll
    for (int o = 16; o > 0; o >>= 1)
        sum += __shfl_xor_sync(0xffffffffu, sum, o);
    if (lane == 0) reds[w] = sum;
    __syncthreads();
    if (t == 0) {
        g_m[row] = bm;
        g_l[row] = reds[0] + reds[1] + reds[2] + reds[3] +
                   reds[4] + reds[5] + reds[6] + reds[7];
    }
}

// K5: AV via split-bf16 mma: O[i0:i0+128, h*64:+64] = softmax(qk) @ V
#define AV_SMEM 104448
__global__ void __launch_bounds__(256, 2)
av_mma_kernel(const float* __restrict__ qk)
{
    extern __shared__ __nv_bfloat16 avs[];
    __nv_bfloat16* sPh = avs;                       // [128][136]
    __nv_bfloat16* sPl = avs + 128 * 136;
    __nv_bfloat16* sVh = avs + 2 * 128 * 136;       // [64][136]
    __nv_bfloat16* sVl = avs + 2 * 128 * 136 + 64 * 136;
    const int i0 = blockIdx.x * 128, h = blockIdx.y;
    const int t = threadIdx.x, wid = t >> 5, lane = t & 31;
    const int wm = wid >> 1, wn = wid & 1;          // warp tile 32(m) x 32(n)

    float acc[2][4][4];
#pragma unroll
    for (int mi = 0; mi < 2; mi++)
#pragma unroll
        for (int o = 0; o < 4; o++)
#pragma unroll
            for (int e = 0; e < 4; e++) acc[mi][o][e] = 0.f;

    for (int jb = 0; jb < 16; jb++) {
        const int j0 = jb * 128;
#pragma unroll
        for (int s = 0; s < 16; s++) {              // P = exp(qk - m), split
            int e = t + 256 * s;
            int r = e >> 5, c4 = e & 31;
            size_t off = ((size_t)(h * 2048 + i0 + r)) * 2048 + j0 + c4 * 4;
            float4 x = *(const float4*)&qk[off];
            float mrow = g_m[h * 2048 + i0 + r];
            float4 p;
            p.x = __expf(x.x - mrow); p.y = __expf(x.y - mrow);
            p.z = __expf(x.z - mrow); p.w = __expf(x.w - mrow);
            split_store(p, &sPh[r * 136 + c4 * 4], &sPl[r * 136 + c4 * 4]);
        }
#pragma unroll
        for (int s = 0; s < 8; s++) {               // V^T tiles hi/lo
            int e = t + 256 * s;
            int d = e >> 5, c4 = e & 31;
            *(uint2*)&sVh[d * 136 + c4 * 4] = *(const uint2*)&g_vth[h][d][j0 + c4 * 4];
            *(uint2*)&sVl[d * 136 + c4 * 4] = *(const uint2*)&g_vtl[h][d][j0 + c4 * 4];
        }
        __syncthreads();
        const uint32_t bPh = smem_u32(sPh), bPl = smem_u32(sPl);
        const uint32_t bVh = smem_u32(sVh), bVl = smem_u32(sVl);
#pragma unroll
        for (int kk = 0; kk < 128; kk += 16) {
            uint32_t ah[2][4], al[2][4], bv[4][2];
#pragma unroll
            for (int mi = 0; mi < 2; mi++) {
                uint32_t off = (uint32_t)((wm * 32 + mi * 16 + (lane & 15)) * 136
                                          + kk + (lane >> 4) * 8) * 2;
                ldm_x4(ah[mi], bPh + off);
                ldm_x4(al[mi], bPl + off);
            }
#pragma unroll
            for (int nb = 0; nb < 2; nb++) {        // Vh frags
                uint32_t off = (uint32_t)((wn * 32 + nb * 16 + (lane & 15)) * 136
                                          + kk + (lane >> 4) * 8) * 2;
                uint32_t r4[4];
                ldm_x4(r4, bVh + off);
                bv[nb * 2 + 0][0] = r4[0]; bv[nb * 2 + 0][1] = r4[2];
                bv[nb * 2 + 1][0] = r4[1]; bv[nb * 2 + 1][1] = r4[3];
            }
#pragma unroll
            for (int mi = 0; mi < 2; mi++)
#pragma unroll
                for (int o = 0; o < 4; o++) {
                    mma_16816(acc[mi][o], ah[mi], bv[o][0], bv[o][1]);
                    mma_16816(acc[mi][o], al[mi], bv[o][0], bv[o][1]);
                }
#pragma unroll
            for (int nb = 0; nb < 2; nb++) {        // Vl frags
                uint32_t off = (uint32_t)((wn * 32 + nb * 16 + (lane & 15)) * 136
                                          + kk + (lane >> 4) * 8) * 2;
                uint32_t r4[4];
                ldm_x4(r4, bVl + off);
                bv[nb * 2 + 0][0] = r4[0]; bv[nb * 2 + 0][1] = r4[2];
                bv[nb * 2 + 1][0] = r4[1]; bv[nb * 2 + 1][1] = r4[3];
            }
#pragma unroll
            for (int mi = 0; mi < 2; mi++)
#pragma unroll
                for (int o = 0; o < 4; o++)
                    mma_16816(acc[mi][o], ah[mi], bv[o][0], bv[o][1]);
        }
        __syncthreads();
    }
#pragma unroll
    for (int mi = 0; mi < 2; mi++)
#pragma unroll
        for (int o = 0; o < 4; o++)
#pragma unroll
            for (int half = 0; half < 2; half++) {
                int row = i0 + wm * 32 + mi * 16 + (lane >> 2) + half * 8;
                float invl = 1.0f / g_l[h * 2048 + row];
                int col = h * 64 + wn * 32 + o * 8 + (lane & 3) * 2;
                float2 w;
                w.x = acc[mi][o][half * 2 + 0] * invl;
                w.y = acc[mi][o][half * 2 + 1] * invl;
                *(float2*)&g_o[row][col] = w;
            }
}

// --------------------------------------------------------------------------
extern "C" void kernel_launch(void* const* d_in, const int* in_sizes, int n_in,
                              void* d_out, int out_size)
{
    const float* x    = (const float*)d_in[0];
    const float* prev = (const float*)d_in[1];
    const float* Wq   = (const float*)d_in[2];
    const float* Wk   = (const float*)d_in[3];
    const float* Wv   = (const float*)d_in[4];
    const float* Wo   = (const float*)d_in[5];
    const float* cq   = (const float*)d_in[6];
    const float* ck   = (const float*)d_in[7];
    const float* cv   = (const float*)d_in[8];
    const float* relw = (const float*)d_in[9];

    float* out = (float*)d_out;                 // (1,2048,1024)
    float* qk  = out + (size_t)NW * NBINS;      // (1,16,2048,2048)

    const size_t QK_SMEM = (size_t)4 * 128 * QK_RS * sizeof(__nv_bfloat16); // 73728
    cudaFuncSetAttribute(proj_mma_kernel, cudaFuncAttributeMaxDynamicSharedMemorySize, GS_SMEM);
    cudaFuncSetAttribute(out_mma_kernel,  cudaFuncAttributeMaxDynamicSharedMemorySize, GS_SMEM);
    cudaFuncSetAttribute(qk_mma_kernel,   cudaFuncAttributeMaxDynamicSharedMemorySize, (int)QK_SMEM);
    cudaFuncSetAttribute(av_mma_kernel,   cudaFuncAttributeMaxDynamicSharedMemorySize, AV_SMEM);

    proj_mma_kernel<<<dim3(8, 16, 3), 256, GS_SMEM>>>(x, Wq, Wk, Wv);
    conv_kernel<<<(3 * NW * NBINS) / 256, 256>>>(cq, ck, cv);
    relw_cvt_kernel<<<(HD * NW) / 256, 256>>>(relw);
    vt_split_kernel<<<dim3(32, 16), 256>>>();
    qk_mma_kernel<<<dim3(16, 16, 16), 256, QK_SMEM>>>(prev, qk);
    rowstat_kernel<<<NH * NW, 256>>>(qk);
    av_mma_kernel<<<dim3(16, 16), 256, AV_SMEM>>>(qk);
    out_mma_kernel<<<dim3(8, 16), 256, GS_SMEM>>>(Wo, out);
}